// round 14
// baseline (speedup 1.0000x reference)
#include <cuda_runtime.h>

#define NN 100000
#define EE 1600000
#define H  128
#define NEGV (-1e30f)
#define SB 128
#define ST 256

// ---------------- device scratch ----------------
__device__ __align__(16) float g_x[(size_t)NN * H];
__device__ __align__(16) float g_y[(size_t)(NN + 128) * H];
__device__ __align__(16) float g_h[(size_t)NN * H];
__device__ float g_dinv[NN];
__device__ int   g_deg[NN];
__device__ int   g_rpA[NN + 1], g_rpB[NN + 1];
__device__ int   g_cursor[NN];
__device__ float g_sp2[NN];
__device__ float g_score[NN];
__device__ unsigned int g_key[NN];
__device__ int g_cmap[NN];
__device__ int g_sel[NN];
__device__ int g_esrc[EE], g_edst[EE];
__device__ int g_csrA[EE], g_csrB[EE];
__device__ unsigned int g_hist[5120];     // zero at load; self-cleaned by selects
__device__ int g_is64;
__device__ int g_bsum[SB];
__device__ long long g_bsum2[SB];
__device__ float g_sum[H], g_max[H], g_rtot[2 * H];
__device__ unsigned int g_barcnt;
__device__ volatile unsigned int g_bargen;

// ---------------- helpers ----------------
__device__ __forceinline__ void atomicMaxF(float* addr, float v) {
    int old = __float_as_int(*addr);
    while (__int_as_float(old) < v) {
        int prev = atomicCAS((int*)addr, old, __float_as_int(v));
        if (prev == old) break;
        old = prev;
    }
}

// barrier among exactly nb participating blocks (must be co-schedulable)
__device__ __forceinline__ void gridbarN(unsigned int nb) {
    __syncthreads();
    if (threadIdx.x == 0) {
        __threadfence();
        unsigned int gen = g_bargen;
        if (atomicAdd(&g_barcnt, 1u) == nb - 1u) {
            g_barcnt = 0u;
            __threadfence();
            g_bargen = gen + 1u;
        } else {
            while (g_bargen == gen) __nanosleep(32);
        }
    }
    __syncthreads();
}

// all-blocks-local digit pick (deterministic, identical across blocks)
__device__ __forceinline__ void pick_local(const unsigned int* gh, int nb,
                                           unsigned int krem_in,
                                           unsigned int* sh, unsigned int* ps,
                                           unsigned int* out_b, unsigned int* out_krem) {
    const int tid = threadIdx.x;
    const int per = nb / ST;
    unsigned int psum = 0;
    for (int j = 0; j < per; j++) {
        unsigned int v = __ldcg(&gh[tid * per + j]);
        sh[tid * per + j] = v;
        psum += v;
    }
    ps[tid] = psum;
    __syncthreads();
    for (int off = 1; off < ST; off <<= 1) {
        unsigned int v = (tid + off < ST) ? ps[tid + off] : 0u;
        __syncthreads();
        ps[tid] += v;
        __syncthreads();
    }
    unsigned int sfx_here = ps[tid];
    unsigned int sfx_next = (tid + 1 < ST) ? ps[tid + 1] : 0u;
    if (sfx_here >= krem_in && sfx_next < krem_in) {
        unsigned int cum = sfx_next;
        int b = tid * per + per - 1;
        for (; b > tid * per; b--) { if (cum + sh[b] >= krem_in) break; cum += sh[b]; }
        *out_b = (unsigned int)b;
        *out_krem = krem_in - cum;
    }
    __syncthreads();
}

// ---------------- GEMM body (raw, no dinv) ----------------
__device__ __forceinline__ void gemm_body(const float* __restrict__ A,
                                          const float* __restrict__ Bm,
                                          int n, int tile) {
    __shared__ float Ast[16][132];
    __shared__ float Bs[16][132];
    const int tid = threadIdx.x;
    const int tx = tid & 15;
    const int ty = tid >> 4;
    const int row0 = tile * 128;
    float acc[8][8];
#pragma unroll
    for (int i = 0; i < 8; i++)
#pragma unroll
        for (int j = 0; j < 8; j++) acc[i][j] = 0.0f;

    for (int k0 = 0; k0 < 128; k0 += 16) {
#pragma unroll
        for (int l = 0; l < 2; l++) {
            int idx = tid + l * 256;
            int r = idx >> 2;
            int c4 = (idx & 3) * 4;
            int gr = row0 + r;
            float4 v = make_float4(0.f, 0.f, 0.f, 0.f);
            if (gr < n) v = *reinterpret_cast<const float4*>(A + (size_t)gr * 128 + k0 + c4);
            Ast[c4 + 0][r] = v.x;
            Ast[c4 + 1][r] = v.y;
            Ast[c4 + 2][r] = v.z;
            Ast[c4 + 3][r] = v.w;
        }
#pragma unroll
        for (int l = 0; l < 2; l++) {
            int idx = tid + l * 256;
            int r = idx >> 5;
            int c4 = (idx & 31) * 4;
            float4 v = *reinterpret_cast<const float4*>(Bm + (size_t)(k0 + r) * 128 + c4);
            *reinterpret_cast<float4*>(&Bs[r][c4]) = v;
        }
        __syncthreads();
#pragma unroll
        for (int kk = 0; kk < 16; kk++) {
            float4 a0 = *reinterpret_cast<const float4*>(&Ast[kk][ty * 8]);
            float4 a1 = *reinterpret_cast<const float4*>(&Ast[kk][ty * 8 + 4]);
            float4 b0 = *reinterpret_cast<const float4*>(&Bs[kk][tx * 8]);
            float4 b1 = *reinterpret_cast<const float4*>(&Bs[kk][tx * 8 + 4]);
            float a[8] = {a0.x, a0.y, a0.z, a0.w, a1.x, a1.y, a1.z, a1.w};
            float bb[8] = {b0.x, b0.y, b0.z, b0.w, b1.x, b1.y, b1.z, b1.w};
#pragma unroll
            for (int i = 0; i < 8; i++)
#pragma unroll
                for (int j = 0; j < 8; j++) acc[i][j] += a[i] * bb[j];
        }
        __syncthreads();
    }
#pragma unroll
    for (int i = 0; i < 8; i++) {
        int gr = row0 + ty * 8 + i;
        if (gr < n) {
            float4 v0 = make_float4(acc[i][0], acc[i][1], acc[i][2], acc[i][3]);
            float4 v1 = make_float4(acc[i][4], acc[i][5], acc[i][6], acc[i][7]);
            *reinterpret_cast<float4*>(g_y + (size_t)gr * 128 + tx * 8) = v0;
            *reinterpret_cast<float4*>(g_y + (size_t)gr * 128 + tx * 8 + 4) = v1;
        }
    }
}

// interleaved block mapping: odd bids < 2*NSIDE are side blocks (wave-1 resident)
__device__ __forceinline__ int side_id(int bid, int nside) {
    if (bid < 2 * nside && (bid & 1)) return bid >> 1;
    return -1;
}
__device__ __forceinline__ int gemm_tile(int bid, int nside) {
    return (bid < 2 * nside) ? (bid >> 1) : (bid - nside);
}

// ---------------- fused layer 0: GEMM || [init -> convert+deg -> scan -> scatter] --------
__global__ void __launch_bounds__(256) k_fuse0(const float* __restrict__ A,
                                               const float* __restrict__ Bm,
                                               int n, int* __restrict__ rowptr,
                                               int* __restrict__ sn,
                                               const void* ei) {
    const int sid = side_id(blockIdx.x, SB);
    if (sid < 0) {
        gemm_body(A, Bm, n, gemm_tile(blockIdx.x, SB));
        return;
    }
    __shared__ int s1[ST];
    __shared__ int sbm[SB];
    const int tid = threadIdx.x;
    const int gt = sid * ST + tid;
    const int gs = SB * ST;

    // ---- P0: per-run init + dtype detect ----
    for (int i = gt; i < NN; i += gs) g_deg[i] = 0;
    if (gt < 2 * H) g_rtot[gt] = 0.0f;
    if (gt < H) { g_sum[gt] = 0.0f; g_max[gt] = NEGV; }
    if (sid == 0 && tid < 32) {
        const long long* p = (const long long*)ei;
        int ok = 1;
        for (int j = tid; j < 1024; j += 32) {
            long long v = p[j];
            if (v < 0 || v >= NN) ok = 0;
        }
        ok = __all_sync(0xffffffffu, ok);
        if (tid == 0) g_is64 = ok;
    }
    gridbarN(SB);

    // ---- P1: convert edges + degree count ----
    if (__ldcg(&g_is64)) {
        const long long* p = (const long long*)ei;
        for (int e = gt; e < EE; e += gs) {
            int s = (int)p[e], d = (int)p[(size_t)EE + e];
            g_esrc[e] = s; g_edst[e] = d;
            atomicAdd(&g_deg[d], 1);
        }
    } else {
        const int* p = (const int*)ei;
        for (int e = gt; e < EE; e += gs) {
            int s = p[e], d = p[(size_t)EE + e];
            g_esrc[e] = s; g_edst[e] = d;
            atomicAdd(&g_deg[d], 1);
        }
    }
    gridbarN(SB);

    // ---- P2: scan -> rowptr / cursor / dinv ----
    const int c = (n + gs - 1) / gs;
    const int lo = min(gt * c, n), hi = min(lo + c, n);
    int cnt = 0;
    for (int i = lo; i < hi; i++) cnt += g_deg[i];
    s1[tid] = cnt; __syncthreads();
    for (int off = 1; off < ST; off <<= 1) {
        int v = (tid >= off) ? s1[tid - off] : 0;
        __syncthreads();
        s1[tid] += v;
        __syncthreads();
    }
    int tpre = s1[tid] - cnt;
    if (tid == 0) g_bsum[sid] = s1[ST - 1];
    gridbarN(SB);
    if (tid < SB) sbm[tid] = __ldcg(&g_bsum[tid]);
    __syncthreads();
    for (int off = 1; off < SB; off <<= 1) {
        int v = (tid >= off && tid < SB) ? sbm[tid - off] : 0;
        __syncthreads();
        if (tid < SB) sbm[tid] += v;
        __syncthreads();
    }
    if (sid == 0 && tid == 0) rowptr[n] = sbm[SB - 1];
    int base = (sid ? sbm[sid - 1] : 0) + tpre;
    for (int i = lo; i < hi; i++) {
        int d = g_deg[i];
        rowptr[i] = base;
        g_cursor[i] = base;
        g_dinv[i] = rsqrtf((float)(1 + d));
        base += d;
    }
    gridbarN(SB);

    // ---- P3: scatter ----
    for (int e = gt; e < EE; e += gs) {
        int pos = atomicAdd(&g_cursor[g_edst[e]], 1);
        sn[pos] = g_esrc[e];
    }
}

// ---------------- fused layers 1/2: GEMM (raw) || CSR rebuild ----------------
__global__ void __launch_bounds__(256) k_fusel(const float* __restrict__ A,
                                               const float* __restrict__ Bm,
                                               int n,
                                               int nold, int nnew,
                                               const int* __restrict__ rpo,
                                               const int* __restrict__ so,
                                               int* __restrict__ rpn,
                                               int* __restrict__ sn) {
    const int sid = side_id(blockIdx.x, SB);
    if (sid < 0) {
        gemm_body(A, Bm, n, gemm_tile(blockIdx.x, SB));
        return;
    }
    __shared__ int s1[ST];
    __shared__ int sbm[SB];
    const int tid = threadIdx.x;
    const int gt = sid * ST + tid;
    const int gs = SB * ST;

    for (int d = gt; d < nold; d += gs) {
        int dn = g_cmap[d];
        if (dn < 0) continue;
        int cnt = 0;
        int r1 = rpo[d + 1];
        for (int e = rpo[d]; e < r1; e++) cnt += (g_cmap[so[e]] >= 0) ? 1 : 0;
        g_deg[dn] = cnt;
    }
    gridbarN(SB);

    const int c = (nnew + gs - 1) / gs;
    const int lo = min(gt * c, nnew), hi = min(lo + c, nnew);
    int cnt = 0;
    for (int i = lo; i < hi; i++) cnt += g_deg[i];
    s1[tid] = cnt; __syncthreads();
    for (int off = 1; off < ST; off <<= 1) {
        int v = (tid >= off) ? s1[tid - off] : 0;
        __syncthreads();
        s1[tid] += v;
        __syncthreads();
    }
    int tpre = s1[tid] - cnt;
    if (tid == 0) g_bsum[sid] = s1[ST - 1];
    gridbarN(SB);
    if (tid < SB) sbm[tid] = __ldcg(&g_bsum[tid]);
    __syncthreads();
    for (int off = 1; off < SB; off <<= 1) {
        int v = (tid >= off && tid < SB) ? sbm[tid - off] : 0;
        __syncthreads();
        if (tid < SB) sbm[tid] += v;
        __syncthreads();
    }
    if (sid == 0 && tid == 0) rpn[nnew] = sbm[SB - 1];
    int base = (sid ? sbm[sid - 1] : 0) + tpre;
    for (int i = lo; i < hi; i++) {
        int d = g_deg[i];
        rpn[i] = base;
        g_dinv[i] = rsqrtf((float)(1 + d));
        base += d;
    }
    gridbarN(SB);

    for (int d = gt; d < nold; d += gs) {
        int dn = g_cmap[d];
        if (dn < 0) continue;
        int pos = rpn[dn];
        int r1 = rpo[d + 1];
        for (int e = rpo[d]; e < r1; e++) {
            int s = g_cmap[so[e]];
            if (s >= 0) sn[pos++] = s;
        }
    }
}

// ---------------- CSR aggregation (per-source dinv) + bias+relu+score-projection ---------
__global__ void __launch_bounds__(256) k_agg(const float* __restrict__ bv,
                                             const float* __restrict__ ws,
                                             const int* __restrict__ rp,
                                             const int* __restrict__ gsrc, int n) {
    int w = (blockIdx.x * 256 + threadIdx.x) >> 5;
    int lane = threadIdx.x & 31;
    if (w >= n) return;
    float di = g_dinv[w];
    int r0 = rp[w], r1 = rp[w + 1];
    float4 yw = reinterpret_cast<const float4*>(g_y)[(size_t)w * 32 + lane];
    float4 acc = make_float4(di * yw.x, di * yw.y, di * yw.z, di * yw.w);
    for (int e = r0; e < r1; e++) {
        int s = gsrc[e];
        float ds = g_dinv[s];
        float4 v = reinterpret_cast<const float4*>(g_y)[(size_t)s * 32 + lane];
        acc.x += ds * v.x; acc.y += ds * v.y; acc.z += ds * v.z; acc.w += ds * v.w;
    }
    float4 bb = reinterpret_cast<const float4*>(bv)[lane];
    float4 hv;
    hv.x = fmaxf(di * acc.x + bb.x, 0.0f);
    hv.y = fmaxf(di * acc.y + bb.y, 0.0f);
    hv.z = fmaxf(di * acc.z + bb.z, 0.0f);
    hv.w = fmaxf(di * acc.w + bb.w, 0.0f);
    reinterpret_cast<float4*>(g_h)[(size_t)w * 32 + lane] = hv;
    float4 wv = reinterpret_cast<const float4*>(ws)[lane];
    float p = hv.x * wv.x + hv.y * wv.y + hv.z * wv.z + hv.w * wv.w;
#pragma unroll
    for (int o = 16; o > 0; o >>= 1) p += __shfl_down_sync(0xffffffffu, p, o);
    if (lane == 0) g_sp2[w] = di * p;
}

// ---------------- persistent select (+ optional inline MLP on last layer) ----------------
__global__ void __launch_bounds__(ST) k_select(int n, int kk,
        const int* __restrict__ rp, const int* __restrict__ csrc,
        const float* __restrict__ bs, int do_mlp,
        const float* __restrict__ M1, const float* __restrict__ bm1,
        const float* __restrict__ M2, const float* __restrict__ bm2,
        const float* __restrict__ M3, const float* __restrict__ bm3,
        float* __restrict__ out) {
    __shared__ unsigned int sh[2048];
    __shared__ unsigned int ps[ST];
    __shared__ unsigned int s_b, s_krem;
    __shared__ long long s2[ST];
    __shared__ long long sb2[SB];
    const int tid = threadIdx.x, bid = blockIdx.x;
    const int gt = bid * ST + tid;
    const int gs = SB * ST;

    // phase 1: score + key + hist (bits 31..21)
    for (int j = tid; j < 2048; j += ST) sh[j] = 0u;
    __syncthreads();
    const float bsv = bs[0];
    for (int i = gt; i < n; i += gs) {
        float acc = g_sp2[i];
        int r1 = rp[i + 1];
        for (int e = rp[i]; e < r1; e++) acc += g_sp2[csrc[e]];
        float sc = g_dinv[i] * acc + bsv;
        g_score[i] = sc;
        unsigned int u = __float_as_uint(sc);
        unsigned int key = (u & 0x80000000u) ? ~u : (u | 0x80000000u);
        g_key[i] = key;
        atomicAdd(&sh[key >> 21], 1u);
    }
    __syncthreads();
    for (int j = tid; j < 2048; j += ST) { unsigned int v = sh[j]; if (v) atomicAdd(&g_hist[j], v); }
    gridbarN(SB);
    pick_local(g_hist, 2048, (unsigned int)kk, sh, ps, &s_b, &s_krem);
    unsigned int b0 = s_b;
    unsigned int krem = s_krem;

    // phase 2: bits 20..10
    for (int j = tid; j < 2048; j += ST) sh[j] = 0u;
    __syncthreads();
    for (int i = gt; i < n; i += gs) {
        unsigned int key = g_key[i];
        if ((key >> 21) == b0) atomicAdd(&sh[(key >> 10) & 0x7FFu], 1u);
    }
    __syncthreads();
    for (int j = tid; j < 2048; j += ST) { unsigned int v = sh[j]; if (v) atomicAdd(&g_hist[2048 + j], v); }
    gridbarN(SB);
    pick_local(g_hist + 2048, 2048, krem, sh, ps, &s_b, &s_krem);
    unsigned int pref20 = (b0 << 11) | s_b;
    krem = s_krem;

    // phase 3: bits 9..0
    for (int j = tid; j < 1024; j += ST) sh[j] = 0u;
    __syncthreads();
    for (int i = gt; i < n; i += gs) {
        unsigned int key = g_key[i];
        if ((key >> 10) == pref20) atomicAdd(&sh[key & 0x3FFu], 1u);
    }
    __syncthreads();
    for (int j = tid; j < 1024; j += ST) { unsigned int v = sh[j]; if (v) atomicAdd(&g_hist[4096 + j], v); }
    gridbarN(SB);
    pick_local(g_hist + 4096, 1024, krem, sh, ps, &s_b, &s_krem);
    const unsigned int T = (pref20 << 10) | s_b;
    const int kremT = (int)s_krem;

    // compaction: (>T, ==T) pair scan
    const int c = (n + gs - 1) / gs;
    const int lo = min(gt * c, n), hi = min(lo + c, n);
    int cgt = 0, ceq = 0;
    for (int i = lo; i < hi; i++) {
        unsigned int key = g_key[i];
        cgt += (key > T) ? 1 : 0;
        ceq += (key == T) ? 1 : 0;
    }
    long long pair = ((long long)cgt << 32) | (unsigned int)ceq;
    s2[tid] = pair; __syncthreads();
    for (int off = 1; off < ST; off <<= 1) {
        long long v = (tid >= off) ? s2[tid - off] : 0;
        __syncthreads();
        s2[tid] += v;
        __syncthreads();
    }
    long long tpre = s2[tid] - pair;
    if (tid == 0) g_bsum2[bid] = s2[ST - 1];
    gridbarN(SB);
    // safe point: all pick_local reads of g_hist are complete -> re-zero for next select
    for (int j = gt; j < 5120; j += gs) g_hist[j] = 0u;
    if (tid < SB) sb2[tid] = __ldcg(&g_bsum2[tid]);
    __syncthreads();
    for (int off = 1; off < SB; off <<= 1) {
        long long v = (tid >= off && tid < SB) ? sb2[tid - off] : 0;
        __syncthreads();
        if (tid < SB) sb2[tid] += v;
        __syncthreads();
    }
    long long basep = (bid ? sb2[bid - 1] : 0) + tpre;
    int bgt = (int)(basep >> 32);
    int beq = (int)(basep & 0xFFFFFFFFll);
    for (int i = lo; i < hi; i++) {
        unsigned int key = g_key[i];
        bool isgt = key > T, iseq = key == T;
        bool sel = isgt || (iseq && beq < kremT);
        int pos = bgt + min(beq, kremT);
        g_cmap[i] = sel ? pos : -1;
        if (sel) g_sel[pos] = i;
        bgt += isgt ? 1 : 0;
        beq += iseq ? 1 : 0;
    }
    gridbarN(SB);

    // pool + readout
    int w = gt >> 5, lane = gt & 31, nw = gs >> 5;
    float4 aS = make_float4(0.f, 0.f, 0.f, 0.f);
    float4 aM = make_float4(NEGV, NEGV, NEGV, NEGV);
    for (int j = w; j < kk; j += nw) {
        int i = g_sel[j];
        float t = tanhf(g_score[i]);
        float4 v = reinterpret_cast<const float4*>(g_h)[(size_t)i * 32 + lane];
        v.x *= t; v.y *= t; v.z *= t; v.w *= t;
        reinterpret_cast<float4*>(g_x)[(size_t)j * 32 + lane] = v;
        aS.x += v.x; aS.y += v.y; aS.z += v.z; aS.w += v.w;
        aM.x = fmaxf(aM.x, v.x); aM.y = fmaxf(aM.y, v.y);
        aM.z = fmaxf(aM.z, v.z); aM.w = fmaxf(aM.w, v.w);
    }
    int col = lane * 4;
    atomicAdd(&g_sum[col + 0], aS.x);
    atomicAdd(&g_sum[col + 1], aS.y);
    atomicAdd(&g_sum[col + 2], aS.z);
    atomicAdd(&g_sum[col + 3], aS.w);
    atomicMaxF(&g_max[col + 0], aM.x);
    atomicMaxF(&g_max[col + 1], aM.y);
    atomicMaxF(&g_max[col + 2], aM.z);
    atomicMaxF(&g_max[col + 3], aM.w);
    gridbarN(SB);
    if (bid != 0) return;

    // readout update (block 0)
    if (tid < H) {
        float s = __ldcg(&g_sum[tid]);
        float m = __ldcg(&g_max[tid]);
        g_rtot[tid] += s / (float)kk;
        g_rtot[H + tid] += m;
        g_sum[tid] = 0.0f;
        g_max[tid] = NEGV;
    }
    if (!do_mlp) return;
    __syncthreads();

    // inline MLP + log_softmax (block 0 only)
    float* f = (float*)sh;          // reuse shared: [0..255] r, [256..383] y1, [384..447] y2, [448..457] y3
    f[tid] = g_rtot[tid];
    __syncthreads();
    if (tid < 128) {
        float a = bm1[tid];
        for (int i = 0; i < 256; i++) a += f[i] * M1[i * 128 + tid];
        f[256 + tid] = fmaxf(a, 0.0f);
    }
    __syncthreads();
    if (tid < 64) {
        float a = bm2[tid];
        for (int i = 0; i < 128; i++) a += f[256 + i] * M2[i * 64 + tid];
        f[384 + tid] = fmaxf(a, 0.0f);
    }
    __syncthreads();
    if (tid < 10) {
        float a = bm3[tid];
        for (int i = 0; i < 64; i++) a += f[384 + i] * M3[i * 10 + tid];
        f[448 + tid] = a;
    }
    __syncthreads();
    if (tid == 0) {
        float m = f[448];
        for (int j = 1; j < 10; j++) m = fmaxf(m, f[448 + j]);
        float s = 0.0f;
        for (int j = 0; j < 10; j++) s += expf(f[448 + j] - m);
        float l = logf(s);
        for (int j = 0; j < 10; j++) out[j] = f[448 + j] - m - l;
    }
}

// ---------------- launch ----------------
extern "C" void kernel_launch(void* const* d_in, const int* in_sizes, int n_in,
                              void* d_out, int out_size) {
    const float* x = (const float*)d_in[0];
    const void* ei = d_in[1];
    const float* W[3]  = {(const float*)d_in[2], (const float*)d_in[6], (const float*)d_in[10]};
    const float* b[3]  = {(const float*)d_in[3], (const float*)d_in[7], (const float*)d_in[11]};
    const float* ws[3] = {(const float*)d_in[4], (const float*)d_in[8], (const float*)d_in[12]};
    const float* bs[3] = {(const float*)d_in[5], (const float*)d_in[9], (const float*)d_in[13]};
    const float* M1 = (const float*)d_in[14]; const float* bm1 = (const float*)d_in[15];
    const float* M2 = (const float*)d_in[16]; const float* bm2 = (const float*)d_in[17];
    const float* M3 = (const float*)d_in[18]; const float* bm3 = (const float*)d_in[19];
    float* out = (float*)d_out;

    int *rpA, *rpB, *csA, *csB;
    float* gx;
    cudaGetSymbolAddress((void**)&rpA, g_rpA);
    cudaGetSymbolAddress((void**)&rpB, g_rpB);
    cudaGetSymbolAddress((void**)&csA, g_csrA);
    cudaGetSymbolAddress((void**)&csB, g_csrB);
    cudaGetSymbolAddress((void**)&gx, g_x);

    const int t0 = (100000 + 127) / 128;
    const int t1 = (50000 + 127) / 128;
    const int t2 = (25000 + 127) / 128;

    // ---- layer 0: GEMM || (init -> convert -> scan -> scatter) ----
    k_fuse0<<<t0 + SB, 256>>>(x, W[0], 100000, rpA, csA, ei);                     // 1
    k_agg<<<(100000 + 7) / 8, 256>>>(b[0], ws[0], rpA, csA, 100000);              // 2
    k_select<<<SB, ST>>>(100000, 50000, rpA, csA, bs[0], 0,
                         M1, bm1, M2, bm2, M3, bm3, out);                          // 3

    // ---- layer 1: GEMM || CSR rebuild ----
    k_fusel<<<t1 + SB, 256>>>(gx, W[1], 50000, 100000, 50000, rpA, csA, rpB, csB); // 4 <- profiled
    k_agg<<<(50000 + 7) / 8, 256>>>(b[1], ws[1], rpB, csB, 50000);
    k_select<<<SB, ST>>>(50000, 25000, rpB, csB, bs[1], 0,
                         M1, bm1, M2, bm2, M3, bm3, out);

    // ---- layer 2: GEMM || CSR rebuild, select + inline MLP ----
    k_fusel<<<t2 + SB, 256>>>(gx, W[2], 25000, 50000, 25000, rpB, csB, rpA, csA);
    k_agg<<<(25000 + 7) / 8, 256>>>(b[2], ws[2], rpA, csA, 25000);
    k_select<<<SB, ST>>>(25000, 12500, rpA, csA, bs[2], 1,
                         M1, bm1, M2, bm2, M3, bm3, out);
}

// round 15
// speedup vs baseline: 1.0238x; 1.0238x over previous
#include <cuda_runtime.h>

#define NN 100000
#define EE 1600000
#define H  128
#define NEGV (-1e30f)
#define SB 128
#define ST 256

// ---------------- device scratch ----------------
__device__ __align__(16) float g_x[(size_t)NN * H];
__device__ __align__(16) float g_y[(size_t)(NN + 128) * H];
__device__ __align__(16) float g_h[(size_t)NN * H];
__device__ float g_dinv[NN];
__device__ int   g_deg[NN];
__device__ int   g_rpA[NN + 1], g_rpB[NN + 1];
__device__ int   g_cursor[NN];
__device__ float g_sp2[NN];
__device__ float g_score[NN];
__device__ unsigned int g_key[NN];
__device__ int g_cmap[NN];
__device__ int g_sel[NN];
__device__ int g_esrc[EE], g_edst[EE];
__device__ int g_csrA[EE], g_csrB[EE];
__device__ unsigned int g_hist[5120];     // zero at load; self-cleaned by selects
__device__ int g_is64;
__device__ int g_bsum[SB];
__device__ long long g_bsum2[SB];
__device__ float g_sum[H], g_max[H], g_rtot[2 * H];
__device__ unsigned int g_barcnt;
__device__ volatile unsigned int g_bargen;

// ---------------- helpers ----------------
__device__ __forceinline__ void atomicMaxF(float* addr, float v) {
    int old = __float_as_int(*addr);
    while (__int_as_float(old) < v) {
        int prev = atomicCAS((int*)addr, old, __float_as_int(v));
        if (prev == old) break;
        old = prev;
    }
}

// barrier among exactly nb participating blocks (must be co-schedulable)
__device__ __forceinline__ void gridbarN(unsigned int nb) {
    __syncthreads();
    if (threadIdx.x == 0) {
        __threadfence();
        unsigned int gen = g_bargen;
        if (atomicAdd(&g_barcnt, 1u) == nb - 1u) {
            g_barcnt = 0u;
            __threadfence();
            g_bargen = gen + 1u;
        } else {
            while (g_bargen == gen) __nanosleep(32);
        }
    }
    __syncthreads();
}

// all-blocks-local digit pick (deterministic, identical across blocks)
__device__ __forceinline__ void pick_local(const unsigned int* gh, int nb,
                                           unsigned int krem_in,
                                           unsigned int* sh, unsigned int* ps,
                                           unsigned int* out_b, unsigned int* out_krem) {
    const int tid = threadIdx.x;
    const int per = nb / ST;
    unsigned int psum = 0;
    for (int j = 0; j < per; j++) {
        unsigned int v = __ldcg(&gh[tid * per + j]);
        sh[tid * per + j] = v;
        psum += v;
    }
    ps[tid] = psum;
    __syncthreads();
    for (int off = 1; off < ST; off <<= 1) {
        unsigned int v = (tid + off < ST) ? ps[tid + off] : 0u;
        __syncthreads();
        ps[tid] += v;
        __syncthreads();
    }
    unsigned int sfx_here = ps[tid];
    unsigned int sfx_next = (tid + 1 < ST) ? ps[tid + 1] : 0u;
    if (sfx_here >= krem_in && sfx_next < krem_in) {
        unsigned int cum = sfx_next;
        int b = tid * per + per - 1;
        for (; b > tid * per; b--) { if (cum + sh[b] >= krem_in) break; cum += sh[b]; }
        *out_b = (unsigned int)b;
        *out_krem = krem_in - cum;
    }
    __syncthreads();
}

// ---------------- GEMM body (raw, no dinv) ----------------
__device__ __forceinline__ void gemm_body(const float* __restrict__ A,
                                          const float* __restrict__ Bm,
                                          int n, int tile) {
    __shared__ float Ast[16][132];
    __shared__ float Bs[16][132];
    const int tid = threadIdx.x;
    const int tx = tid & 15;
    const int ty = tid >> 4;
    const int row0 = tile * 128;
    float acc[8][8];
#pragma unroll
    for (int i = 0; i < 8; i++)
#pragma unroll
        for (int j = 0; j < 8; j++) acc[i][j] = 0.0f;

    for (int k0 = 0; k0 < 128; k0 += 16) {
#pragma unroll
        for (int l = 0; l < 2; l++) {
            int idx = tid + l * 256;
            int r = idx >> 2;
            int c4 = (idx & 3) * 4;
            int gr = row0 + r;
            float4 v = make_float4(0.f, 0.f, 0.f, 0.f);
            if (gr < n) v = *reinterpret_cast<const float4*>(A + (size_t)gr * 128 + k0 + c4);
            Ast[c4 + 0][r] = v.x;
            Ast[c4 + 1][r] = v.y;
            Ast[c4 + 2][r] = v.z;
            Ast[c4 + 3][r] = v.w;
        }
#pragma unroll
        for (int l = 0; l < 2; l++) {
            int idx = tid + l * 256;
            int r = idx >> 5;
            int c4 = (idx & 31) * 4;
            float4 v = *reinterpret_cast<const float4*>(Bm + (size_t)(k0 + r) * 128 + c4);
            *reinterpret_cast<float4*>(&Bs[r][c4]) = v;
        }
        __syncthreads();
#pragma unroll
        for (int kk = 0; kk < 16; kk++) {
            float4 a0 = *reinterpret_cast<const float4*>(&Ast[kk][ty * 8]);
            float4 a1 = *reinterpret_cast<const float4*>(&Ast[kk][ty * 8 + 4]);
            float4 b0 = *reinterpret_cast<const float4*>(&Bs[kk][tx * 8]);
            float4 b1 = *reinterpret_cast<const float4*>(&Bs[kk][tx * 8 + 4]);
            float a[8] = {a0.x, a0.y, a0.z, a0.w, a1.x, a1.y, a1.z, a1.w};
            float bb[8] = {b0.x, b0.y, b0.z, b0.w, b1.x, b1.y, b1.z, b1.w};
#pragma unroll
            for (int i = 0; i < 8; i++)
#pragma unroll
                for (int j = 0; j < 8; j++) acc[i][j] += a[i] * bb[j];
        }
        __syncthreads();
    }
#pragma unroll
    for (int i = 0; i < 8; i++) {
        int gr = row0 + ty * 8 + i;
        if (gr < n) {
            float4 v0 = make_float4(acc[i][0], acc[i][1], acc[i][2], acc[i][3]);
            float4 v1 = make_float4(acc[i][4], acc[i][5], acc[i][6], acc[i][7]);
            *reinterpret_cast<float4*>(g_y + (size_t)gr * 128 + tx * 8) = v0;
            *reinterpret_cast<float4*>(g_y + (size_t)gr * 128 + tx * 8 + 4) = v1;
        }
    }
}

// interleaved block mapping: odd bids < 2*NSIDE are side blocks (wave-1 resident)
__device__ __forceinline__ int side_id(int bid, int nside) {
    if (bid < 2 * nside && (bid & 1)) return bid >> 1;
    return -1;
}
__device__ __forceinline__ int gemm_tile(int bid, int nside) {
    return (bid < 2 * nside) ? (bid >> 1) : (bid - nside);
}

// ---------------- fused layer 0: GEMM || [init -> convert+deg -> scan -> scatter] --------
__global__ void __launch_bounds__(256) k_fuse0(const float* __restrict__ A,
                                               const float* __restrict__ Bm,
                                               int n, int* __restrict__ rowptr,
                                               int* __restrict__ sn,
                                               const void* ei) {
    const int sid = side_id(blockIdx.x, SB);
    if (sid < 0) {
        gemm_body(A, Bm, n, gemm_tile(blockIdx.x, SB));
        return;
    }
    __shared__ int s1[ST];
    __shared__ int sbm[SB];
    const int tid = threadIdx.x;
    const int gt = sid * ST + tid;
    const int gs = SB * ST;

    // ---- P0: per-run init + dtype detect ----
    for (int i = gt; i < NN; i += gs) g_deg[i] = 0;
    if (gt < 2 * H) g_rtot[gt] = 0.0f;
    if (gt < H) { g_sum[gt] = 0.0f; g_max[gt] = NEGV; }
    if (sid == 0 && tid < 32) {
        const long long* p = (const long long*)ei;
        int ok = 1;
        for (int j = tid; j < 1024; j += 32) {
            long long v = p[j];
            if (v < 0 || v >= NN) ok = 0;
        }
        ok = __all_sync(0xffffffffu, ok);
        if (tid == 0) g_is64 = ok;
    }
    gridbarN(SB);

    // ---- P1: convert edges + degree count ----
    if (__ldcg(&g_is64)) {
        const long long* p = (const long long*)ei;
        for (int e = gt; e < EE; e += gs) {
            int s = (int)p[e], d = (int)p[(size_t)EE + e];
            g_esrc[e] = s; g_edst[e] = d;
            atomicAdd(&g_deg[d], 1);
        }
    } else {
        const int* p = (const int*)ei;
        for (int e = gt; e < EE; e += gs) {
            int s = p[e], d = p[(size_t)EE + e];
            g_esrc[e] = s; g_edst[e] = d;
            atomicAdd(&g_deg[d], 1);
        }
    }
    gridbarN(SB);

    // ---- P2: scan -> rowptr / cursor / dinv ----
    const int c = (n + gs - 1) / gs;
    const int lo = min(gt * c, n), hi = min(lo + c, n);
    int cnt = 0;
    for (int i = lo; i < hi; i++) cnt += g_deg[i];
    s1[tid] = cnt; __syncthreads();
    for (int off = 1; off < ST; off <<= 1) {
        int v = (tid >= off) ? s1[tid - off] : 0;
        __syncthreads();
        s1[tid] += v;
        __syncthreads();
    }
    int tpre = s1[tid] - cnt;
    if (tid == 0) g_bsum[sid] = s1[ST - 1];
    gridbarN(SB);
    if (tid < SB) sbm[tid] = __ldcg(&g_bsum[tid]);
    __syncthreads();
    for (int off = 1; off < SB; off <<= 1) {
        int v = (tid >= off && tid < SB) ? sbm[tid - off] : 0;
        __syncthreads();
        if (tid < SB) sbm[tid] += v;
        __syncthreads();
    }
    if (sid == 0 && tid == 0) rowptr[n] = sbm[SB - 1];
    int base = (sid ? sbm[sid - 1] : 0) + tpre;
    for (int i = lo; i < hi; i++) {
        int d = g_deg[i];
        rowptr[i] = base;
        g_cursor[i] = base;
        g_dinv[i] = rsqrtf((float)(1 + d));
        base += d;
    }
    gridbarN(SB);

    // ---- P3: scatter ----
    for (int e = gt; e < EE; e += gs) {
        int pos = atomicAdd(&g_cursor[g_edst[e]], 1);
        sn[pos] = g_esrc[e];
    }
}

// ---------------- fused layers 1/2: GEMM (raw) || CSR scan+scatter (deg precomputed) -----
__global__ void __launch_bounds__(256) k_fusel(const float* __restrict__ A,
                                               const float* __restrict__ Bm,
                                               int n,
                                               int nold, int nnew,
                                               const int* __restrict__ rpo,
                                               const int* __restrict__ so,
                                               int* __restrict__ rpn,
                                               int* __restrict__ sn) {
    const int sid = side_id(blockIdx.x, SB);
    if (sid < 0) {
        gemm_body(A, Bm, n, gemm_tile(blockIdx.x, SB));
        return;
    }
    __shared__ int s1[ST];
    __shared__ int sbm[SB];
    const int tid = threadIdx.x;
    const int gt = sid * ST + tid;
    const int gs = SB * ST;

    // scan over nnew (g_deg precomputed by previous select) -> rpn + dinv
    const int c = (nnew + gs - 1) / gs;
    const int lo = min(gt * c, nnew), hi = min(lo + c, nnew);
    int cnt = 0;
    for (int i = lo; i < hi; i++) cnt += g_deg[i];
    s1[tid] = cnt; __syncthreads();
    for (int off = 1; off < ST; off <<= 1) {
        int v = (tid >= off) ? s1[tid - off] : 0;
        __syncthreads();
        s1[tid] += v;
        __syncthreads();
    }
    int tpre = s1[tid] - cnt;
    if (tid == 0) g_bsum[sid] = s1[ST - 1];
    gridbarN(SB);
    if (tid < SB) sbm[tid] = __ldcg(&g_bsum[tid]);
    __syncthreads();
    for (int off = 1; off < SB; off <<= 1) {
        int v = (tid >= off && tid < SB) ? sbm[tid - off] : 0;
        __syncthreads();
        if (tid < SB) sbm[tid] += v;
        __syncthreads();
    }
    if (sid == 0 && tid == 0) rpn[nnew] = sbm[SB - 1];
    int base = (sid ? sbm[sid - 1] : 0) + tpre;
    for (int i = lo; i < hi; i++) {
        int d = g_deg[i];
        rpn[i] = base;
        g_dinv[i] = rsqrtf((float)(1 + d));
        base += d;
    }
    gridbarN(SB);

    // scatter (owner-sequential, no atomics)
    for (int d = gt; d < nold; d += gs) {
        int dn = g_cmap[d];
        if (dn < 0) continue;
        int pos = rpn[dn];
        int r1 = rpo[d + 1];
        for (int e = rpo[d]; e < r1; e++) {
            int s = g_cmap[so[e]];
            if (s >= 0) sn[pos++] = s;
        }
    }
}

// ---------------- CSR aggregation (per-source dinv) + bias+relu+score-projection ---------
__global__ void __launch_bounds__(256) k_agg(const float* __restrict__ bv,
                                             const float* __restrict__ ws,
                                             const int* __restrict__ rp,
                                             const int* __restrict__ gsrc, int n) {
    int w = (blockIdx.x * 256 + threadIdx.x) >> 5;
    int lane = threadIdx.x & 31;
    if (w >= n) return;
    float di = g_dinv[w];
    int r0 = rp[w], r1 = rp[w + 1];
    float4 yw = reinterpret_cast<const float4*>(g_y)[(size_t)w * 32 + lane];
    float4 acc = make_float4(di * yw.x, di * yw.y, di * yw.z, di * yw.w);
    for (int e = r0; e < r1; e++) {
        int s = gsrc[e];
        float ds = g_dinv[s];
        float4 v = reinterpret_cast<const float4*>(g_y)[(size_t)s * 32 + lane];
        acc.x += ds * v.x; acc.y += ds * v.y; acc.z += ds * v.z; acc.w += ds * v.w;
    }
    float4 bb = reinterpret_cast<const float4*>(bv)[lane];
    float4 hv;
    hv.x = fmaxf(di * acc.x + bb.x, 0.0f);
    hv.y = fmaxf(di * acc.y + bb.y, 0.0f);
    hv.z = fmaxf(di * acc.z + bb.z, 0.0f);
    hv.w = fmaxf(di * acc.w + bb.w, 0.0f);
    reinterpret_cast<float4*>(g_h)[(size_t)w * 32 + lane] = hv;
    float4 wv = reinterpret_cast<const float4*>(ws)[lane];
    float p = hv.x * wv.x + hv.y * wv.y + hv.z * wv.z + hv.w * wv.w;
#pragma unroll
    for (int o = 16; o > 0; o >>= 1) p += __shfl_down_sync(0xffffffffu, p, o);
    if (lane == 0) g_sp2[w] = di * p;
}

// ---------------- persistent select (+ deg precompute for next layer; inline MLP on last)
__global__ void __launch_bounds__(ST) k_select(int n, int kk,
        const int* __restrict__ rp, const int* __restrict__ csrc,
        const float* __restrict__ bs, int do_mlp,
        const float* __restrict__ M1, const float* __restrict__ bm1,
        const float* __restrict__ M2, const float* __restrict__ bm2,
        const float* __restrict__ M3, const float* __restrict__ bm3,
        float* __restrict__ out) {
    __shared__ unsigned int sh[2048];
    __shared__ unsigned int ps[ST];
    __shared__ unsigned int s_b, s_krem;
    __shared__ long long s2[ST];
    __shared__ long long sb2[SB];
    const int tid = threadIdx.x, bid = blockIdx.x;
    const int gt = bid * ST + tid;
    const int gs = SB * ST;

    // phase 1: score + key + hist (bits 31..21)
    for (int j = tid; j < 2048; j += ST) sh[j] = 0u;
    __syncthreads();
    const float bsv = bs[0];
    for (int i = gt; i < n; i += gs) {
        float acc = g_sp2[i];
        int r1 = rp[i + 1];
        for (int e = rp[i]; e < r1; e++) acc += g_sp2[csrc[e]];
        float sc = g_dinv[i] * acc + bsv;
        g_score[i] = sc;
        unsigned int u = __float_as_uint(sc);
        unsigned int key = (u & 0x80000000u) ? ~u : (u | 0x80000000u);
        g_key[i] = key;
        atomicAdd(&sh[key >> 21], 1u);
    }
    __syncthreads();
    for (int j = tid; j < 2048; j += ST) { unsigned int v = sh[j]; if (v) atomicAdd(&g_hist[j], v); }
    gridbarN(SB);
    pick_local(g_hist, 2048, (unsigned int)kk, sh, ps, &s_b, &s_krem);
    unsigned int b0 = s_b;
    unsigned int krem = s_krem;

    // phase 2: bits 20..10
    for (int j = tid; j < 2048; j += ST) sh[j] = 0u;
    __syncthreads();
    for (int i = gt; i < n; i += gs) {
        unsigned int key = g_key[i];
        if ((key >> 21) == b0) atomicAdd(&sh[(key >> 10) & 0x7FFu], 1u);
    }
    __syncthreads();
    for (int j = tid; j < 2048; j += ST) { unsigned int v = sh[j]; if (v) atomicAdd(&g_hist[2048 + j], v); }
    gridbarN(SB);
    pick_local(g_hist + 2048, 2048, krem, sh, ps, &s_b, &s_krem);
    unsigned int pref20 = (b0 << 11) | s_b;
    krem = s_krem;

    // phase 3: bits 9..0
    for (int j = tid; j < 1024; j += ST) sh[j] = 0u;
    __syncthreads();
    for (int i = gt; i < n; i += gs) {
        unsigned int key = g_key[i];
        if ((key >> 10) == pref20) atomicAdd(&sh[key & 0x3FFu], 1u);
    }
    __syncthreads();
    for (int j = tid; j < 1024; j += ST) { unsigned int v = sh[j]; if (v) atomicAdd(&g_hist[4096 + j], v); }
    gridbarN(SB);
    pick_local(g_hist + 4096, 1024, krem, sh, ps, &s_b, &s_krem);
    const unsigned int T = (pref20 << 10) | s_b;
    const int kremT = (int)s_krem;

    // compaction: (>T, ==T) pair scan
    const int c = (n + gs - 1) / gs;
    const int lo = min(gt * c, n), hi = min(lo + c, n);
    int cgt = 0, ceq = 0;
    for (int i = lo; i < hi; i++) {
        unsigned int key = g_key[i];
        cgt += (key > T) ? 1 : 0;
        ceq += (key == T) ? 1 : 0;
    }
    long long pair = ((long long)cgt << 32) | (unsigned int)ceq;
    s2[tid] = pair; __syncthreads();
    for (int off = 1; off < ST; off <<= 1) {
        long long v = (tid >= off) ? s2[tid - off] : 0;
        __syncthreads();
        s2[tid] += v;
        __syncthreads();
    }
    long long tpre = s2[tid] - pair;
    if (tid == 0) g_bsum2[bid] = s2[ST - 1];
    gridbarN(SB);
    // safe point: all pick_local reads of g_hist are complete -> re-zero for next select
    for (int j = gt; j < 5120; j += gs) g_hist[j] = 0u;
    if (tid < SB) sb2[tid] = __ldcg(&g_bsum2[tid]);
    __syncthreads();
    for (int off = 1; off < SB; off <<= 1) {
        long long v = (tid >= off && tid < SB) ? sb2[tid - off] : 0;
        __syncthreads();
        if (tid < SB) sb2[tid] += v;
        __syncthreads();
    }
    long long basep = (bid ? sb2[bid - 1] : 0) + tpre;
    int bgt = (int)(basep >> 32);
    int beq = (int)(basep & 0xFFFFFFFFll);
    for (int i = lo; i < hi; i++) {
        unsigned int key = g_key[i];
        bool isgt = key > T, iseq = key == T;
        bool sel = isgt || (iseq && beq < kremT);
        int pos = bgt + min(beq, kremT);
        g_cmap[i] = sel ? pos : -1;
        if (sel) g_sel[pos] = i;
        bgt += isgt ? 1 : 0;
        beq += iseq ? 1 : 0;
    }
    gridbarN(SB);

    // pool + readout (+ next-layer deg precompute, overlapped)
    int w = gt >> 5, lane = gt & 31, nw = gs >> 5;
    float4 aS = make_float4(0.f, 0.f, 0.f, 0.f);
    float4 aM = make_float4(NEGV, NEGV, NEGV, NEGV);
    for (int j = w; j < kk; j += nw) {
        int i = g_sel[j];
        float t = tanhf(g_score[i]);
        float4 v = reinterpret_cast<const float4*>(g_h)[(size_t)i * 32 + lane];
        v.x *= t; v.y *= t; v.z *= t; v.w *= t;
        reinterpret_cast<float4*>(g_x)[(size_t)j * 32 + lane] = v;
        aS.x += v.x; aS.y += v.y; aS.z += v.z; aS.w += v.w;
        aM.x = fmaxf(aM.x, v.x); aM.y = fmaxf(aM.y, v.y);
        aM.z = fmaxf(aM.z, v.z); aM.w = fmaxf(aM.w, v.w);
    }
    if (!do_mlp) {
        // deg for next layer: every new node dn has exactly one old owner -> plain write
        for (int d = gt; d < n; d += gs) {
            int dn = g_cmap[d];
            if (dn < 0) continue;
            int cnt = 0;
            int r1 = rp[d + 1];
            for (int e = rp[d]; e < r1; e++) cnt += (g_cmap[csrc[e]] >= 0) ? 1 : 0;
            g_deg[dn] = cnt;
        }
    }
    int col = lane * 4;
    atomicAdd(&g_sum[col + 0], aS.x);
    atomicAdd(&g_sum[col + 1], aS.y);
    atomicAdd(&g_sum[col + 2], aS.z);
    atomicAdd(&g_sum[col + 3], aS.w);
    atomicMaxF(&g_max[col + 0], aM.x);
    atomicMaxF(&g_max[col + 1], aM.y);
    atomicMaxF(&g_max[col + 2], aM.z);
    atomicMaxF(&g_max[col + 3], aM.w);
    gridbarN(SB);
    if (bid != 0) return;

    // readout update (block 0)
    if (tid < H) {
        float s = __ldcg(&g_sum[tid]);
        float m = __ldcg(&g_max[tid]);
        g_rtot[tid] += s / (float)kk;
        g_rtot[H + tid] += m;
        g_sum[tid] = 0.0f;
        g_max[tid] = NEGV;
    }
    if (!do_mlp) return;
    __syncthreads();

    // inline MLP + log_softmax (block 0 only)
    float* f = (float*)sh;
    f[tid] = g_rtot[tid];
    __syncthreads();
    if (tid < 128) {
        float a = bm1[tid];
        for (int i = 0; i < 256; i++) a += f[i] * M1[i * 128 + tid];
        f[256 + tid] = fmaxf(a, 0.0f);
    }
    __syncthreads();
    if (tid < 64) {
        float a = bm2[tid];
        for (int i = 0; i < 128; i++) a += f[256 + i] * M2[i * 64 + tid];
        f[384 + tid] = fmaxf(a, 0.0f);
    }
    __syncthreads();
    if (tid < 10) {
        float a = bm3[tid];
        for (int i = 0; i < 64; i++) a += f[384 + i] * M3[i * 10 + tid];
        f[448 + tid] = a;
    }
    __syncthreads();
    if (tid == 0) {
        float m = f[448];
        for (int j = 1; j < 10; j++) m = fmaxf(m, f[448 + j]);
        float s = 0.0f;
        for (int j = 0; j < 10; j++) s += expf(f[448 + j] - m);
        float l = logf(s);
        for (int j = 0; j < 10; j++) out[j] = f[448 + j] - m - l;
    }
}

// ---------------- launch ----------------
extern "C" void kernel_launch(void* const* d_in, const int* in_sizes, int n_in,
                              void* d_out, int out_size) {
    const float* x = (const float*)d_in[0];
    const void* ei = d_in[1];
    const float* W[3]  = {(const float*)d_in[2], (const float*)d_in[6], (const float*)d_in[10]};
    const float* b[3]  = {(const float*)d_in[3], (const float*)d_in[7], (const float*)d_in[11]};
    const float* ws[3] = {(const float*)d_in[4], (const float*)d_in[8], (const float*)d_in[12]};
    const float* bs[3] = {(const float*)d_in[5], (const float*)d_in[9], (const float*)d_in[13]};
    const float* M1 = (const float*)d_in[14]; const float* bm1 = (const float*)d_in[15];
    const float* M2 = (const float*)d_in[16]; const float* bm2 = (const float*)d_in[17];
    const float* M3 = (const float*)d_in[18]; const float* bm3 = (const float*)d_in[19];
    float* out = (float*)d_out;

    int *rpA, *rpB, *csA, *csB;
    float* gx;
    cudaGetSymbolAddress((void**)&rpA, g_rpA);
    cudaGetSymbolAddress((void**)&rpB, g_rpB);
    cudaGetSymbolAddress((void**)&csA, g_csrA);
    cudaGetSymbolAddress((void**)&csB, g_csrB);
    cudaGetSymbolAddress((void**)&gx, g_x);

    const int t0 = (100000 + 127) / 128;
    const int t1 = (50000 + 127) / 128;
    const int t2 = (25000 + 127) / 128;

    // ---- layer 0 ----
    k_fuse0<<<t0 + SB, 256>>>(x, W[0], 100000, rpA, csA, ei);
    k_agg<<<(100000 + 7) / 8, 256>>>(b[0], ws[0], rpA, csA, 100000);
    k_select<<<SB, ST>>>(100000, 50000, rpA, csA, bs[0], 0,
                         M1, bm1, M2, bm2, M3, bm3, out);

    // ---- layer 1 ----
    k_fusel<<<t1 + SB, 256>>>(gx, W[1], 50000, 100000, 50000, rpA, csA, rpB, csB);
    k_agg<<<(50000 + 7) / 8, 256>>>(b[1], ws[1], rpB, csB, 50000);
    k_select<<<SB, ST>>>(50000, 25000, rpB, csB, bs[1], 0,
                         M1, bm1, M2, bm2, M3, bm3, out);

    // ---- layer 2 ----
    k_fusel<<<t2 + SB, 256>>>(gx, W[2], 25000, 50000, 25000, rpB, csB, rpA, csA);
    k_agg<<<(25000 + 7) / 8, 256>>>(b[2], ws[2], rpA, csA, 25000);
    k_select<<<SB, ST>>>(25000, 12500, rpA, csA, bs[2], 1,
                         M1, bm1, M2, bm2, M3, bm3, out);
}